// round 1
// baseline (speedup 1.0000x reference)
#include <cuda_runtime.h>
#include <math.h>

#define NMAX 100000
#define HID 64
#define NGRAPHS 64
#define JKDIM 192

// ---------------- scratch (device globals: no allocation allowed) ----------
__device__ int   g_deg[NMAX];
__device__ float g_dinv[NMAX];
__device__ float g_ys [(size_t)NMAX * HID];
__device__ float g_acc[(size_t)NMAX * HID];
__device__ float g_h  [(size_t)NMAX * HID];
__device__ float g_pooled[NGRAPHS * JKDIM];
__device__ float g_cnt[NGRAPHS];

// ---------------- init ------------------------------------------------------
__global__ void zero_kernel(int N) {
    int i = blockIdx.x * blockDim.x + threadIdx.x;
    if (i < N) g_deg[i] = 0;
    if (i < NGRAPHS * JKDIM) g_pooled[i] = 0.f;
    if (i < NGRAPHS) g_cnt[i] = 0.f;
}

__global__ void degree_kernel(const int* __restrict__ ei, int E) {
    int e = blockIdx.x * blockDim.x + threadIdx.x;
    if (e < E) atomicAdd(&g_deg[ei[E + e]], 1);
}

__global__ void dinv_kernel(int N) {
    int n = blockIdx.x * blockDim.x + threadIdx.x;
    if (n < N) g_dinv[n] = rsqrtf((float)(g_deg[n] + 1));  // +1 self loop
}

// ---------------- GEMM: ys = acc = (A @ W) * dinv[row]  --------------------
// A: [N, KTOT] fp32 (A==nullptr -> use g_h), W: [KTOT, 64]
// tile: 128 rows x 64 cols, 256 threads, 8x4 micro-tile, K chunks of 32.
template <int KTOT>
__global__ __launch_bounds__(256) void gemm_scale(const float* __restrict__ A,
                                                  const float* __restrict__ W,
                                                  int N) {
    __shared__ float Ask[32][131];   // [k][row], pad 131 for conflict-free
    __shared__ float Ws[32][64];

    const float* __restrict__ Ap = A ? A : g_h;

    int tid = threadIdx.x;
    int tx = tid & 15;      // col group (4 cols)
    int ty = tid >> 4;      // row group (8 rows)
    int rowBase = blockIdx.x * 128;

    float acc[8][4];
#pragma unroll
    for (int i = 0; i < 8; i++)
#pragma unroll
        for (int j = 0; j < 4; j++) acc[i][j] = 0.f;

    for (int kc = 0; kc < KTOT; kc += 32) {
        // load A chunk: 128 rows x 32 k, transposed into Ask[k][row]
        {
            int k8 = tid & 7;       // which float4 in the 32-k chunk
            int r0 = tid >> 3;      // 0..31
#pragma unroll
            for (int p = 0; p < 4; p++) {
                int r = r0 + p * 32;
                int grow = rowBase + r;
                float4 v = make_float4(0.f, 0.f, 0.f, 0.f);
                if (grow < N)
                    v = *(const float4*)(Ap + (size_t)grow * KTOT + kc + k8 * 4);
                Ask[k8 * 4 + 0][r] = v.x;
                Ask[k8 * 4 + 1][r] = v.y;
                Ask[k8 * 4 + 2][r] = v.z;
                Ask[k8 * 4 + 3][r] = v.w;
            }
        }
        // load W chunk: 32 k x 64 cols
        {
            int c4 = tid & 15;
            int kr = tid >> 4;   // 0..15
#pragma unroll
            for (int p = 0; p < 2; p++) {
                int k = kr + p * 16;
                *(float4*)&Ws[k][c4 * 4] =
                    *(const float4*)(W + (size_t)(kc + k) * 64 + c4 * 4);
            }
        }
        __syncthreads();
#pragma unroll
        for (int kk = 0; kk < 32; kk++) {
            float4 w = *(const float4*)&Ws[kk][tx * 4];
#pragma unroll
            for (int i = 0; i < 8; i++) {
                float a = Ask[kk][ty * 8 + i];
                acc[i][0] += a * w.x;
                acc[i][1] += a * w.y;
                acc[i][2] += a * w.z;
                acc[i][3] += a * w.w;
            }
        }
        __syncthreads();
    }

#pragma unroll
    for (int i = 0; i < 8; i++) {
        int row = rowBase + ty * 8 + i;
        if (row < N) {
            float dv = g_dinv[row];
            float4 v;
            v.x = acc[i][0] * dv;
            v.y = acc[i][1] * dv;
            v.z = acc[i][2] * dv;
            v.w = acc[i][3] * dv;
            *(float4*)(g_ys + (size_t)row * HID + tx * 4) = v;
            *(float4*)(g_acc + (size_t)row * HID + tx * 4) = v;  // self-loop init
        }
    }
}

// ---------------- edge scatter: acc[dst] += ys[src] -------------------------
__global__ void scatter_kernel(const int* __restrict__ ei, int E) {
    long long gid = (long long)blockIdx.x * blockDim.x + threadIdx.x;
    int e = (int)(gid >> 4);
    if (e >= E) return;
    int f = ((int)gid & 15) * 4;
    int s = __ldg(ei + e);
    int d = __ldg(ei + E + e);
    float4 v = *(const float4*)(g_ys + (size_t)s * HID + f);
    float* p = g_acc + (size_t)d * HID + f;
    asm volatile("red.global.add.v4.f32 [%0], {%1,%2,%3,%4};"
                 :: "l"(p), "f"(v.x), "f"(v.y), "f"(v.z), "f"(v.w)
                 : "memory");
}

// ---------------- epilogue: h = relu(acc * dinv + b) ------------------------
__global__ void epilogue_relu(const float* __restrict__ bias, int N) {
    int gid = blockIdx.x * blockDim.x + threadIdx.x;
    int n = gid >> 4;
    if (n >= N) return;
    int f = (gid & 15) * 4;
    float dv = g_dinv[n];
    float4 a = *(const float4*)(g_acc + (size_t)n * HID + f);
    float4 b = *(const float4*)(bias + f);
    float4 h;
    h.x = fmaxf(a.x * dv + b.x, 0.f);
    h.y = fmaxf(a.y * dv + b.y, 0.f);
    h.z = fmaxf(a.z * dv + b.z, 0.f);
    h.w = fmaxf(a.w * dv + b.w, 0.f);
    *(float4*)(g_h + (size_t)n * HID + f) = h;
}

// ---------------- segmented pooling (batch is sorted) -----------------------
// block handles 1024 rows; thread t: feature f = t&63, row substream rs = t>>6
__global__ void pool_kernel(const int* __restrict__ batch, int off, int doCount,
                            int N) {
    int f = threadIdx.x & 63;
    int rs = threadIdx.x >> 6;
    int base = blockIdx.x * 1024;
    int end = min(base + 1024, N);
    float sum = 0.f, cacc = 0.f;
    int curg = -1;
    for (int r = base + rs; r < end; r += 4) {
        int g = batch[r];
        if (g != curg) {
            if (curg >= 0) {
                atomicAdd(&g_pooled[curg * JKDIM + off + f], sum);
                if (doCount && f == 0) atomicAdd(&g_cnt[curg], cacc);
            }
            sum = 0.f;
            cacc = 0.f;
            curg = g;
        }
        sum += g_h[(size_t)r * HID + f];
        cacc += 1.f;
    }
    if (curg >= 0) {
        atomicAdd(&g_pooled[curg * JKDIM + off + f], sum);
        if (doCount && f == 0) atomicAdd(&g_cnt[curg], cacc);
    }
}

// ---------------- head: mean-pool normalize + linear + log_softmax ----------
__global__ void head_kernel(const float* __restrict__ Wl,
                            const float* __restrict__ bl,
                            float* __restrict__ out) {
    int g = threadIdx.x;
    if (g >= NGRAPHS) return;
    float ic = 1.f / fmaxf(g_cnt[g], 1.f);
    float logit[10];
#pragma unroll
    for (int j = 0; j < 10; j++) logit[j] = bl[j];
    for (int k = 0; k < JKDIM; k++) {
        float v = g_pooled[g * JKDIM + k] * ic;
#pragma unroll
        for (int j = 0; j < 10; j++) logit[j] += v * Wl[k * 10 + j];
    }
    float m = logit[0];
#pragma unroll
    for (int j = 1; j < 10; j++) m = fmaxf(m, logit[j]);
    float s = 0.f;
#pragma unroll
    for (int j = 0; j < 10; j++) s += expf(logit[j] - m);
    float lse = logf(s);
#pragma unroll
    for (int j = 0; j < 10; j++) out[g * 10 + j] = logit[j] - m - lse;
}

// ---------------- launch -----------------------------------------------------
extern "C" void kernel_launch(void* const* d_in, const int* in_sizes, int n_in,
                              void* d_out, int out_size) {
    const float* x  = (const float*)d_in[0];
    const float* W1 = (const float*)d_in[1];
    const float* b1 = (const float*)d_in[2];
    const float* W2 = (const float*)d_in[3];
    const float* b2 = (const float*)d_in[4];
    const float* W3 = (const float*)d_in[5];
    const float* b3 = (const float*)d_in[6];
    const float* W4 = (const float*)d_in[7];
    const float* b4 = (const float*)d_in[8];
    const float* Wl = (const float*)d_in[9];
    const float* bl = (const float*)d_in[10];
    const int* ei    = (const int*)d_in[11];
    const int* batch = (const int*)d_in[12];
    float* out = (float*)d_out;

    int N = in_sizes[12];       // batch has N entries
    int E = in_sizes[11] / 2;   // edge_index is [2, E]

    int threads = 256;
    int gridN = (N + threads - 1) / threads;
    int gridE = (E + threads - 1) / threads;
    int gemmGrid = (N + 127) / 128;
    long long scatThreads = (long long)E * 16;
    int scatGrid = (int)((scatThreads + threads - 1) / threads);
    int epiGrid = (N * 16 + threads - 1) / threads;
    int poolGrid = (N + 1023) / 1024;

    zero_kernel<<<gridN, threads>>>(N);
    degree_kernel<<<gridE, threads>>>(ei, E);
    dinv_kernel<<<gridN, threads>>>(N);

    // layer 1 (input x, K=128)
    gemm_scale<128><<<gemmGrid, 256>>>(x, W1, N);
    scatter_kernel<<<scatGrid, threads>>>(ei, E);
    epilogue_relu<<<epiGrid, threads>>>(b1, N);
    pool_kernel<<<poolGrid, 256>>>(batch, 0, 1, N);   // x1 -> [0:64), also counts

    // layer 2
    gemm_scale<64><<<gemmGrid, 256>>>(nullptr, W2, N);
    scatter_kernel<<<scatGrid, threads>>>(ei, E);
    epilogue_relu<<<epiGrid, threads>>>(b2, N);
    pool_kernel<<<poolGrid, 256>>>(batch, 64, 0, N);  // x2 -> [64:128)

    // layer 3
    gemm_scale<64><<<gemmGrid, 256>>>(nullptr, W3, N);
    scatter_kernel<<<scatGrid, threads>>>(ei, E);
    epilogue_relu<<<epiGrid, threads>>>(b3, N);

    // layer 4 (overwrites x3, as in reference)
    gemm_scale<64><<<gemmGrid, 256>>>(nullptr, W4, N);
    scatter_kernel<<<scatGrid, threads>>>(ei, E);
    epilogue_relu<<<epiGrid, threads>>>(b4, N);
    pool_kernel<<<poolGrid, 256>>>(batch, 128, 0, N); // final x3 -> [128:192)

    head_kernel<<<1, 64>>>(Wl, bl, out);
}

// round 2
// speedup vs baseline: 1.0909x; 1.0909x over previous
#include <cuda_runtime.h>
#include <math.h>

#define NMAX 100000
#define EMAX 1600000
#define HID 64
#define NGRAPHS 64
#define JKDIM 192

// ---------------- scratch (device globals: no allocation allowed) ----------
__device__ int   g_deg[NMAX];
__device__ int   g_rowptr[NMAX + 1];
__device__ int   g_cursor[NMAX];
__device__ int   g_csr_src[EMAX];
__device__ float g_dinv[NMAX];
__device__ float g_ys[(size_t)NMAX * HID];
__device__ float g_h [(size_t)NMAX * HID];
__device__ float g_pooled[NGRAPHS * JKDIM];
__device__ float g_cnt[NGRAPHS];

// ---------------- init ------------------------------------------------------
__global__ void zero_kernel(int N) {
    int i = blockIdx.x * blockDim.x + threadIdx.x;
    if (i < N) g_deg[i] = 0;
    if (i < NGRAPHS * JKDIM) g_pooled[i] = 0.f;
    if (i < NGRAPHS) g_cnt[i] = 0.f;
}

__global__ void degree_kernel(const int* __restrict__ ei, int E) {
    int e = blockIdx.x * blockDim.x + threadIdx.x;
    if (e < E) atomicAdd(&g_deg[ei[E + e]], 1);
}

__global__ void dinv_kernel(int N) {
    int n = blockIdx.x * blockDim.x + threadIdx.x;
    if (n < N) g_dinv[n] = rsqrtf((float)(g_deg[n] + 1));  // +1 self loop
}

// single-block prefix scan of degrees -> rowptr, cursor
__global__ void scan_kernel(int N) {
    __shared__ int bs[1024];
    int t = threadIdx.x;
    int chunk = (N + 1023) / 1024;
    int lo = t * chunk, hi = min(lo + chunk, N);
    int sum = 0;
    for (int i = lo; i < hi; i++) sum += g_deg[i];
    bs[t] = sum;
    __syncthreads();
    for (int off = 1; off < 1024; off <<= 1) {
        int v = (t >= off) ? bs[t - off] : 0;
        __syncthreads();
        if (t >= off) bs[t] += v;
        __syncthreads();
    }
    int run = (t > 0) ? bs[t - 1] : 0;
    for (int i = lo; i < hi; i++) {
        g_rowptr[i] = run;
        g_cursor[i] = run;
        run += g_deg[i];
    }
    if (t == 1023) g_rowptr[N] = bs[1023];
}

__global__ void fill_kernel(const int* __restrict__ ei, int E) {
    int e = blockIdx.x * blockDim.x + threadIdx.x;
    if (e < E) {
        int d = ei[E + e];
        int pos = atomicAdd(&g_cursor[d], 1);
        g_csr_src[pos] = ei[e];
    }
}

// ---------------- GEMM: ys = (A @ W) * dinv[row]  ---------------------------
// A: [N, KTOT] fp32 (A==nullptr -> use g_h), W: [KTOT, 64]
// tile: 128 rows x 64 cols, 256 threads, 8x4 micro-tile, K chunks of 32.
template <int KTOT>
__global__ __launch_bounds__(256) void gemm_scale(const float* __restrict__ A,
                                                  const float* __restrict__ W,
                                                  int N) {
    __shared__ float Ask[32][132];   // [k][row], 132 keeps float4 loads aligned
    __shared__ float Ws[32][64];

    const float* __restrict__ Ap = A ? A : g_h;

    int tid = threadIdx.x;
    int tx = tid & 15;      // col group (4 cols)
    int ty = tid >> 4;      // row group (8 rows)
    int rowBase = blockIdx.x * 128;

    float acc[8][4];
#pragma unroll
    for (int i = 0; i < 8; i++)
#pragma unroll
        for (int j = 0; j < 4; j++) acc[i][j] = 0.f;

    for (int kc = 0; kc < KTOT; kc += 32) {
        {
            int k8 = tid & 7;       // which float4 in the 32-k chunk
            int r0 = tid >> 3;      // 0..31
#pragma unroll
            for (int p = 0; p < 4; p++) {
                int r = r0 + p * 32;
                int grow = rowBase + r;
                float4 v = make_float4(0.f, 0.f, 0.f, 0.f);
                if (grow < N)
                    v = *(const float4*)(Ap + (size_t)grow * KTOT + kc + k8 * 4);
                Ask[k8 * 4 + 0][r] = v.x;
                Ask[k8 * 4 + 1][r] = v.y;
                Ask[k8 * 4 + 2][r] = v.z;
                Ask[k8 * 4 + 3][r] = v.w;
            }
        }
        {
            int c4 = tid & 15;
            int kr = tid >> 4;   // 0..15
#pragma unroll
            for (int p = 0; p < 2; p++) {
                int k = kr + p * 16;
                *(float4*)&Ws[k][c4 * 4] =
                    *(const float4*)(W + (size_t)(kc + k) * 64 + c4 * 4);
            }
        }
        __syncthreads();
#pragma unroll
        for (int kk = 0; kk < 32; kk++) {
            float4 w = *(const float4*)&Ws[kk][tx * 4];
            float4 a0 = *(const float4*)&Ask[kk][ty * 8];
            float4 a1 = *(const float4*)&Ask[kk][ty * 8 + 4];
            float av[8] = {a0.x, a0.y, a0.z, a0.w, a1.x, a1.y, a1.z, a1.w};
#pragma unroll
            for (int i = 0; i < 8; i++) {
                acc[i][0] += av[i] * w.x;
                acc[i][1] += av[i] * w.y;
                acc[i][2] += av[i] * w.z;
                acc[i][3] += av[i] * w.w;
            }
        }
        __syncthreads();
    }

#pragma unroll
    for (int i = 0; i < 8; i++) {
        int row = rowBase + ty * 8 + i;
        if (row < N) {
            float dv = g_dinv[row];
            float4 v;
            v.x = acc[i][0] * dv;
            v.y = acc[i][1] * dv;
            v.z = acc[i][2] * dv;
            v.w = acc[i][3] * dv;
            *(float4*)(g_ys + (size_t)row * HID + tx * 4) = v;
        }
    }
}

// ---- aggregation (pull mode): h[n] = relu(dinv*(ys[n] + sum ys[src]) + b) --
__global__ void aggregate_kernel(const float* __restrict__ bias, int N) {
    int gid = blockIdx.x * blockDim.x + threadIdx.x;
    int node = gid >> 4;
    if (node >= N) return;
    int f4 = (gid & 15) * 4;

    int beg = __ldg(&g_rowptr[node]);
    int end = __ldg(&g_rowptr[node + 1]);

    float4 s0 = *(const float4*)(g_ys + (size_t)node * HID + f4);  // self loop
    float4 s1 = make_float4(0.f, 0.f, 0.f, 0.f);
    float4 s2 = make_float4(0.f, 0.f, 0.f, 0.f);
    float4 s3 = make_float4(0.f, 0.f, 0.f, 0.f);

    int e = beg;
    for (; e + 4 <= end; e += 4) {
        int a = __ldg(&g_csr_src[e]);
        int b = __ldg(&g_csr_src[e + 1]);
        int c = __ldg(&g_csr_src[e + 2]);
        int d = __ldg(&g_csr_src[e + 3]);
        float4 v0 = *(const float4*)(g_ys + (size_t)a * HID + f4);
        float4 v1 = *(const float4*)(g_ys + (size_t)b * HID + f4);
        float4 v2 = *(const float4*)(g_ys + (size_t)c * HID + f4);
        float4 v3 = *(const float4*)(g_ys + (size_t)d * HID + f4);
        s0.x += v0.x; s0.y += v0.y; s0.z += v0.z; s0.w += v0.w;
        s1.x += v1.x; s1.y += v1.y; s1.z += v1.z; s1.w += v1.w;
        s2.x += v2.x; s2.y += v2.y; s2.z += v2.z; s2.w += v2.w;
        s3.x += v3.x; s3.y += v3.y; s3.z += v3.z; s3.w += v3.w;
    }
    for (; e < end; e++) {
        int a = __ldg(&g_csr_src[e]);
        float4 v = *(const float4*)(g_ys + (size_t)a * HID + f4);
        s0.x += v.x; s0.y += v.y; s0.z += v.z; s0.w += v.w;
    }
    s0.x += s1.x + s2.x + s3.x;
    s0.y += s1.y + s2.y + s3.y;
    s0.z += s1.z + s2.z + s3.z;
    s0.w += s1.w + s2.w + s3.w;

    float dv = g_dinv[node];
    float4 b4 = *(const float4*)(bias + f4);
    float4 h;
    h.x = fmaxf(s0.x * dv + b4.x, 0.f);
    h.y = fmaxf(s0.y * dv + b4.y, 0.f);
    h.z = fmaxf(s0.z * dv + b4.z, 0.f);
    h.w = fmaxf(s0.w * dv + b4.w, 0.f);
    *(float4*)(g_h + (size_t)node * HID + f4) = h;
}

// ---------------- segmented pooling (batch is sorted) -----------------------
__global__ void pool_kernel(const int* __restrict__ batch, int off, int doCount,
                            int N) {
    int f = threadIdx.x & 63;
    int rs = threadIdx.x >> 6;
    int base = blockIdx.x * 1024;
    int end = min(base + 1024, N);
    float sum = 0.f, cacc = 0.f;
    int curg = -1;
    for (int r = base + rs; r < end; r += 4) {
        int g = batch[r];
        if (g != curg) {
            if (curg >= 0) {
                atomicAdd(&g_pooled[curg * JKDIM + off + f], sum);
                if (doCount && f == 0) atomicAdd(&g_cnt[curg], cacc);
            }
            sum = 0.f;
            cacc = 0.f;
            curg = g;
        }
        sum += g_h[(size_t)r * HID + f];
        cacc += 1.f;
    }
    if (curg >= 0) {
        atomicAdd(&g_pooled[curg * JKDIM + off + f], sum);
        if (doCount && f == 0) atomicAdd(&g_cnt[curg], cacc);
    }
}

// ---------------- head: mean-pool normalize + linear + log_softmax ----------
__global__ void head_kernel(const float* __restrict__ Wl,
                            const float* __restrict__ bl,
                            float* __restrict__ out) {
    int g = threadIdx.x;
    if (g >= NGRAPHS) return;
    float ic = 1.f / fmaxf(g_cnt[g], 1.f);
    float logit[10];
#pragma unroll
    for (int j = 0; j < 10; j++) logit[j] = bl[j];
    for (int k = 0; k < JKDIM; k++) {
        float v = g_pooled[g * JKDIM + k] * ic;
#pragma unroll
        for (int j = 0; j < 10; j++) logit[j] += v * Wl[k * 10 + j];
    }
    float m = logit[0];
#pragma unroll
    for (int j = 1; j < 10; j++) m = fmaxf(m, logit[j]);
    float s = 0.f;
#pragma unroll
    for (int j = 0; j < 10; j++) s += expf(logit[j] - m);
    float lse = logf(s);
#pragma unroll
    for (int j = 0; j < 10; j++) out[g * 10 + j] = logit[j] - m - lse;
}

// ---------------- launch -----------------------------------------------------
extern "C" void kernel_launch(void* const* d_in, const int* in_sizes, int n_in,
                              void* d_out, int out_size) {
    const float* x  = (const float*)d_in[0];
    const float* W1 = (const float*)d_in[1];
    const float* b1 = (const float*)d_in[2];
    const float* W2 = (const float*)d_in[3];
    const float* b2 = (const float*)d_in[4];
    const float* W3 = (const float*)d_in[5];
    const float* b3 = (const float*)d_in[6];
    const float* W4 = (const float*)d_in[7];
    const float* b4 = (const float*)d_in[8];
    const float* Wl = (const float*)d_in[9];
    const float* bl = (const float*)d_in[10];
    const int* ei    = (const int*)d_in[11];
    const int* batch = (const int*)d_in[12];
    float* out = (float*)d_out;

    int N = in_sizes[12];       // batch has N entries
    int E = in_sizes[11] / 2;   // edge_index is [2, E]

    int threads = 256;
    int gridN = (N + threads - 1) / threads;
    int gridE = (E + threads - 1) / threads;
    int gemmGrid = (N + 127) / 128;
    int aggGrid = (N * 16 + threads - 1) / threads;
    int poolGrid = (N + 1023) / 1024;

    zero_kernel<<<gridN, threads>>>(N);
    degree_kernel<<<gridE, threads>>>(ei, E);
    dinv_kernel<<<gridN, threads>>>(N);
    scan_kernel<<<1, 1024>>>(N);
    fill_kernel<<<gridE, threads>>>(ei, E);

    // layer 1 (input x, K=128)
    gemm_scale<128><<<gemmGrid, 256>>>(x, W1, N);
    aggregate_kernel<<<aggGrid, threads>>>(b1, N);
    pool_kernel<<<poolGrid, 256>>>(batch, 0, 1, N);   // x1 -> [0:64), also counts

    // layer 2
    gemm_scale<64><<<gemmGrid, 256>>>(nullptr, W2, N);
    aggregate_kernel<<<aggGrid, threads>>>(b2, N);
    pool_kernel<<<poolGrid, 256>>>(batch, 64, 0, N);  // x2 -> [64:128)

    // layer 3
    gemm_scale<64><<<gemmGrid, 256>>>(nullptr, W3, N);
    aggregate_kernel<<<aggGrid, threads>>>(b3, N);

    // layer 4 (overwrites x3, as in reference)
    gemm_scale<64><<<gemmGrid, 256>>>(nullptr, W4, N);
    aggregate_kernel<<<aggGrid, threads>>>(b4, N);
    pool_kernel<<<poolGrid, 256>>>(batch, 128, 0, N); // final x3 -> [128:192)

    head_kernel<<<1, 64>>>(Wl, bl, out);
}

// round 3
// speedup vs baseline: 1.4177x; 1.2996x over previous
#include <cuda_runtime.h>
#include <math.h>

#define NMAX 100000
#define EMAX 1600000
#define HID 64
#define NGRAPHS 64
#define JKDIM 192
#define SCAN_BLK 1024
#define MAX_SCAN_BLOCKS 128

// ---------------- scratch (device globals: no allocation allowed) ----------
__device__ int   g_deg[NMAX];
__device__ int   g_rowptr[NMAX + 1];
__device__ int   g_cursor[NMAX];
__device__ int   g_scanloc[NMAX];
__device__ int   g_blocksum[MAX_SCAN_BLOCKS];
__device__ int   g_blockoff[MAX_SCAN_BLOCKS];
__device__ int   g_csr_src[EMAX];
__device__ float g_dinv[NMAX];
__device__ float g_ys[(size_t)NMAX * HID];
__device__ float g_h [(size_t)NMAX * HID];
__device__ float g_pooled[NGRAPHS * JKDIM];
__device__ float g_cnt[NGRAPHS];

// ---------------- init ------------------------------------------------------
__global__ void zero_kernel(int N) {
    int i = blockIdx.x * blockDim.x + threadIdx.x;
    if (i < N) g_deg[i] = 0;
    if (i < NGRAPHS * JKDIM) g_pooled[i] = 0.f;
    if (i < NGRAPHS) g_cnt[i] = 0.f;
}

__global__ void degree_kernel(const int* __restrict__ ei, int E) {
    int e = blockIdx.x * blockDim.x + threadIdx.x;
    if (e < E) atomicAdd(&g_deg[ei[E + e]], 1);
}

__global__ void dinv_kernel(int N) {
    int n = blockIdx.x * blockDim.x + threadIdx.x;
    if (n < N) g_dinv[n] = rsqrtf((float)(g_deg[n] + 1));  // +1 self loop
}

// ---------------- 3-phase grid-wide exclusive scan of g_deg -> g_rowptr -----
__global__ __launch_bounds__(SCAN_BLK) void block_scan_kernel(int N) {
    __shared__ int bs[SCAN_BLK];
    int t = threadIdx.x;
    int i = blockIdx.x * SCAN_BLK + t;
    int v = (i < N) ? g_deg[i] : 0;
    bs[t] = v;
    __syncthreads();
#pragma unroll
    for (int off = 1; off < SCAN_BLK; off <<= 1) {
        int u = (t >= off) ? bs[t - off] : 0;
        __syncthreads();
        bs[t] += u;
        __syncthreads();
    }
    if (i < N) g_scanloc[i] = bs[t] - v;   // exclusive within block
    if (t == SCAN_BLK - 1) g_blocksum[blockIdx.x] = bs[t];
}

__global__ void scan_blocksums_kernel(int nb) {
    __shared__ int bs[MAX_SCAN_BLOCKS];
    int t = threadIdx.x;
    int v = (t < nb) ? g_blocksum[t] : 0;
    bs[t] = v;
    __syncthreads();
#pragma unroll
    for (int off = 1; off < MAX_SCAN_BLOCKS; off <<= 1) {
        int u = (t >= off) ? bs[t - off] : 0;
        __syncthreads();
        bs[t] += u;
        __syncthreads();
    }
    if (t < nb) g_blockoff[t] = bs[t] - v;  // exclusive
}

__global__ void apply_offsets_kernel(int N, int E) {
    int i = blockIdx.x * blockDim.x + threadIdx.x;
    if (i < N) {
        int r = g_scanloc[i] + g_blockoff[i / SCAN_BLK];
        g_rowptr[i] = r;
        g_cursor[i] = r;
    }
    if (i == 0) g_rowptr[N] = E;
}

__global__ void fill_kernel(const int* __restrict__ ei, int E) {
    int e = blockIdx.x * blockDim.x + threadIdx.x;
    if (e < E) {
        int d = ei[E + e];
        int pos = atomicAdd(&g_cursor[d], 1);
        g_csr_src[pos] = ei[e];
    }
}

// ---------------- GEMM: ys = (A @ W) * dinv[row]  ---------------------------
template <int KTOT>
__global__ __launch_bounds__(256) void gemm_scale(const float* __restrict__ A,
                                                  const float* __restrict__ W,
                                                  int N) {
    __shared__ float Ask[32][132];
    __shared__ float Ws[32][64];

    const float* __restrict__ Ap = A ? A : g_h;

    int tid = threadIdx.x;
    int tx = tid & 15;
    int ty = tid >> 4;
    int rowBase = blockIdx.x * 128;

    float acc[8][4];
#pragma unroll
    for (int i = 0; i < 8; i++)
#pragma unroll
        for (int j = 0; j < 4; j++) acc[i][j] = 0.f;

    for (int kc = 0; kc < KTOT; kc += 32) {
        {
            int k8 = tid & 7;
            int r0 = tid >> 3;
#pragma unroll
            for (int p = 0; p < 4; p++) {
                int r = r0 + p * 32;
                int grow = rowBase + r;
                float4 v = make_float4(0.f, 0.f, 0.f, 0.f);
                if (grow < N)
                    v = *(const float4*)(Ap + (size_t)grow * KTOT + kc + k8 * 4);
                Ask[k8 * 4 + 0][r] = v.x;
                Ask[k8 * 4 + 1][r] = v.y;
                Ask[k8 * 4 + 2][r] = v.z;
                Ask[k8 * 4 + 3][r] = v.w;
            }
        }
        {
            int c4 = tid & 15;
            int kr = tid >> 4;
#pragma unroll
            for (int p = 0; p < 2; p++) {
                int k = kr + p * 16;
                *(float4*)&Ws[k][c4 * 4] =
                    *(const float4*)(W + (size_t)(kc + k) * 64 + c4 * 4);
            }
        }
        __syncthreads();
#pragma unroll
        for (int kk = 0; kk < 32; kk++) {
            float4 w = *(const float4*)&Ws[kk][tx * 4];
            float4 a0 = *(const float4*)&Ask[kk][ty * 8];
            float4 a1 = *(const float4*)&Ask[kk][ty * 8 + 4];
            float av[8] = {a0.x, a0.y, a0.z, a0.w, a1.x, a1.y, a1.z, a1.w};
#pragma unroll
            for (int i = 0; i < 8; i++) {
                acc[i][0] += av[i] * w.x;
                acc[i][1] += av[i] * w.y;
                acc[i][2] += av[i] * w.z;
                acc[i][3] += av[i] * w.w;
            }
        }
        __syncthreads();
    }

#pragma unroll
    for (int i = 0; i < 8; i++) {
        int row = rowBase + ty * 8 + i;
        if (row < N) {
            float dv = g_dinv[row];
            float4 v;
            v.x = acc[i][0] * dv;
            v.y = acc[i][1] * dv;
            v.z = acc[i][2] * dv;
            v.w = acc[i][3] * dv;
            *(float4*)(g_ys + (size_t)row * HID + tx * 4) = v;
        }
    }
}

// ---- aggregation (pull mode): h[n] = relu(dinv*(ys[n] + sum ys[src]) + b) --
__global__ void aggregate_kernel(const float* __restrict__ bias, int N) {
    int gid = blockIdx.x * blockDim.x + threadIdx.x;
    int node = gid >> 4;
    if (node >= N) return;
    int f4 = (gid & 15) * 4;

    int beg = __ldg(&g_rowptr[node]);
    int end = __ldg(&g_rowptr[node + 1]);

    float4 s0 = *(const float4*)(g_ys + (size_t)node * HID + f4);  // self loop
    float4 s1 = make_float4(0.f, 0.f, 0.f, 0.f);
    float4 s2 = make_float4(0.f, 0.f, 0.f, 0.f);
    float4 s3 = make_float4(0.f, 0.f, 0.f, 0.f);

    int e = beg;
    for (; e + 4 <= end; e += 4) {
        int a = __ldg(&g_csr_src[e]);
        int b = __ldg(&g_csr_src[e + 1]);
        int c = __ldg(&g_csr_src[e + 2]);
        int d = __ldg(&g_csr_src[e + 3]);
        float4 v0 = *(const float4*)(g_ys + (size_t)a * HID + f4);
        float4 v1 = *(const float4*)(g_ys + (size_t)b * HID + f4);
        float4 v2 = *(const float4*)(g_ys + (size_t)c * HID + f4);
        float4 v3 = *(const float4*)(g_ys + (size_t)d * HID + f4);
        s0.x += v0.x; s0.y += v0.y; s0.z += v0.z; s0.w += v0.w;
        s1.x += v1.x; s1.y += v1.y; s1.z += v1.z; s1.w += v1.w;
        s2.x += v2.x; s2.y += v2.y; s2.z += v2.z; s2.w += v2.w;
        s3.x += v3.x; s3.y += v3.y; s3.z += v3.z; s3.w += v3.w;
    }
    for (; e < end; e++) {
        int a = __ldg(&g_csr_src[e]);
        float4 v = *(const float4*)(g_ys + (size_t)a * HID + f4);
        s0.x += v.x; s0.y += v.y; s0.z += v.z; s0.w += v.w;
    }
    s0.x += s1.x + s2.x + s3.x;
    s0.y += s1.y + s2.y + s3.y;
    s0.z += s1.z + s2.z + s3.z;
    s0.w += s1.w + s2.w + s3.w;

    float dv = g_dinv[node];
    float4 b4 = *(const float4*)(bias + f4);
    float4 h;
    h.x = fmaxf(s0.x * dv + b4.x, 0.f);
    h.y = fmaxf(s0.y * dv + b4.y, 0.f);
    h.z = fmaxf(s0.z * dv + b4.z, 0.f);
    h.w = fmaxf(s0.w * dv + b4.w, 0.f);
    *(float4*)(g_h + (size_t)node * HID + f4) = h;
}

// ---------------- segmented pooling (batch is sorted) -----------------------
__global__ void pool_kernel(const int* __restrict__ batch, int off, int doCount,
                            int N) {
    int f = threadIdx.x & 63;
    int rs = threadIdx.x >> 6;
    int base = blockIdx.x * 1024;
    int end = min(base + 1024, N);
    float sum = 0.f, cacc = 0.f;
    int curg = -1;
    for (int r = base + rs; r < end; r += 4) {
        int g = batch[r];
        if (g != curg) {
            if (curg >= 0) {
                atomicAdd(&g_pooled[curg * JKDIM + off + f], sum);
                if (doCount && f == 0) atomicAdd(&g_cnt[curg], cacc);
            }
            sum = 0.f;
            cacc = 0.f;
            curg = g;
        }
        sum += g_h[(size_t)r * HID + f];
        cacc += 1.f;
    }
    if (curg >= 0) {
        atomicAdd(&g_pooled[curg * JKDIM + off + f], sum);
        if (doCount && f == 0) atomicAdd(&g_cnt[curg], cacc);
    }
}

// ---------------- head: mean-pool normalize + linear + log_softmax ----------
__global__ void head_kernel(const float* __restrict__ Wl,
                            const float* __restrict__ bl,
                            float* __restrict__ out) {
    int g = threadIdx.x;
    if (g >= NGRAPHS) return;
    float ic = 1.f / fmaxf(g_cnt[g], 1.f);
    float logit[10];
#pragma unroll
    for (int j = 0; j < 10; j++) logit[j] = bl[j];
    for (int k = 0; k < JKDIM; k++) {
        float v = g_pooled[g * JKDIM + k] * ic;
#pragma unroll
        for (int j = 0; j < 10; j++) logit[j] += v * Wl[k * 10 + j];
    }
    float m = logit[0];
#pragma unroll
    for (int j = 1; j < 10; j++) m = fmaxf(m, logit[j]);
    float s = 0.f;
#pragma unroll
    for (int j = 0; j < 10; j++) s += expf(logit[j] - m);
    float lse = logf(s);
#pragma unroll
    for (int j = 0; j < 10; j++) out[g * 10 + j] = logit[j] - m - lse;
}

// ---------------- launch -----------------------------------------------------
extern "C" void kernel_launch(void* const* d_in, const int* in_sizes, int n_in,
                              void* d_out, int out_size) {
    const float* x  = (const float*)d_in[0];
    const float* W1 = (const float*)d_in[1];
    const float* b1 = (const float*)d_in[2];
    const float* W2 = (const float*)d_in[3];
    const float* b2 = (const float*)d_in[4];
    const float* W3 = (const float*)d_in[5];
    const float* b3 = (const float*)d_in[6];
    const float* W4 = (const float*)d_in[7];
    const float* b4 = (const float*)d_in[8];
    const float* Wl = (const float*)d_in[9];
    const float* bl = (const float*)d_in[10];
    const int* ei    = (const int*)d_in[11];
    const int* batch = (const int*)d_in[12];
    float* out = (float*)d_out;

    int N = in_sizes[12];       // batch has N entries
    int E = in_sizes[11] / 2;   // edge_index is [2, E]

    int threads = 256;
    int gridN = (N + threads - 1) / threads;
    int gridE = (E + threads - 1) / threads;
    int gemmGrid = (N + 127) / 128;
    int aggGrid = (N * 16 + threads - 1) / threads;
    int poolGrid = (N + 1023) / 1024;
    int nScanBlocks = (N + SCAN_BLK - 1) / SCAN_BLK;

    zero_kernel<<<gridN, threads>>>(N);
    degree_kernel<<<gridE, threads>>>(ei, E);
    dinv_kernel<<<gridN, threads>>>(N);
    block_scan_kernel<<<nScanBlocks, SCAN_BLK>>>(N);
    scan_blocksums_kernel<<<1, MAX_SCAN_BLOCKS>>>(nScanBlocks);
    apply_offsets_kernel<<<gridN, threads>>>(N, E);
    fill_kernel<<<gridE, threads>>>(ei, E);

    // layer 1 (input x, K=128)
    gemm_scale<128><<<gemmGrid, 256>>>(x, W1, N);
    aggregate_kernel<<<aggGrid, threads>>>(b1, N);
    pool_kernel<<<poolGrid, 256>>>(batch, 0, 1, N);   // x1 -> [0:64), also counts

    // layer 2
    gemm_scale<64><<<gemmGrid, 256>>>(nullptr, W2, N);
    aggregate_kernel<<<aggGrid, threads>>>(b2, N);
    pool_kernel<<<poolGrid, 256>>>(batch, 64, 0, N);  // x2 -> [64:128)

    // layer 3
    gemm_scale<64><<<gemmGrid, 256>>>(nullptr, W3, N);
    aggregate_kernel<<<aggGrid, threads>>>(b3, N);

    // layer 4 (overwrites x3, as in reference)
    gemm_scale<64><<<gemmGrid, 256>>>(nullptr, W4, N);
    aggregate_kernel<<<aggGrid, threads>>>(b4, N);
    pool_kernel<<<poolGrid, 256>>>(batch, 128, 0, N); // final x3 -> [128:192)

    head_kernel<<<1, 64>>>(Wl, bl, out);
}

// round 4
// speedup vs baseline: 2.4412x; 1.7219x over previous
#include <cuda_runtime.h>
#include <math.h>

#define NMAX 100000
#define EMAX 1600000
#define HID 64
#define NGRAPHS 64
#define JKDIM 192
#define SCAN_BLK 1024
#define MAX_SCAN_BLOCKS 128

// ---------------- scratch (device globals: no allocation allowed) ----------
__device__ int   g_deg[NMAX];
__device__ int   g_rowptr[NMAX + 1];
__device__ int   g_cursor[NMAX];
__device__ int   g_scanloc[NMAX];
__device__ int   g_blocksum[MAX_SCAN_BLOCKS];
__device__ int   g_blockoff[MAX_SCAN_BLOCKS];
__device__ int   g_csr_src[EMAX];
__device__ float g_dinv[NMAX];
__device__ float g_ys[(size_t)NMAX * HID];
__device__ float g_h [(size_t)NMAX * HID];
__device__ float g_pooled[NGRAPHS * JKDIM];
__device__ float g_cnt[NGRAPHS];

// ---------------- f32x2 helpers ---------------------------------------------
__device__ __forceinline__ unsigned long long pack2(float lo, float hi) {
    unsigned long long r;
    asm("mov.b64 %0, {%1, %2};" : "=l"(r) : "f"(lo), "f"(hi));
    return r;
}
__device__ __forceinline__ void unpack2(unsigned long long v, float& lo, float& hi) {
    asm("mov.b64 {%0, %1}, %2;" : "=f"(lo), "=f"(hi) : "l"(v));
}
__device__ __forceinline__ void fma2(unsigned long long& d, unsigned long long a,
                                     unsigned long long b) {
    asm("fma.rn.f32x2 %0, %1, %2, %0;" : "+l"(d) : "l"(a), "l"(b));
}

// ---------------- init ------------------------------------------------------
__global__ void zero_kernel(int N) {
    int i = blockIdx.x * blockDim.x + threadIdx.x;
    if (i < N) g_deg[i] = 0;
    if (i < NGRAPHS * JKDIM) g_pooled[i] = 0.f;
    if (i < NGRAPHS) g_cnt[i] = 0.f;
}

__global__ void degree_kernel(const int* __restrict__ ei, int E) {
    int e = blockIdx.x * blockDim.x + threadIdx.x;
    if (e < E) atomicAdd(&g_deg[ei[E + e]], 1);
}

__global__ void dinv_kernel(int N) {
    int n = blockIdx.x * blockDim.x + threadIdx.x;
    if (n < N) g_dinv[n] = rsqrtf((float)(g_deg[n] + 1));  // +1 self loop
}

// ---------------- 3-phase grid-wide exclusive scan of g_deg -> g_rowptr -----
__global__ __launch_bounds__(SCAN_BLK) void block_scan_kernel(int N) {
    __shared__ int bs[SCAN_BLK];
    int t = threadIdx.x;
    int i = blockIdx.x * SCAN_BLK + t;
    int v = (i < N) ? g_deg[i] : 0;
    bs[t] = v;
    __syncthreads();
#pragma unroll
    for (int off = 1; off < SCAN_BLK; off <<= 1) {
        int u = (t >= off) ? bs[t - off] : 0;
        __syncthreads();
        bs[t] += u;
        __syncthreads();
    }
    if (i < N) g_scanloc[i] = bs[t] - v;
    if (t == SCAN_BLK - 1) g_blocksum[blockIdx.x] = bs[t];
}

__global__ void scan_blocksums_kernel(int nb) {
    __shared__ int bs[MAX_SCAN_BLOCKS];
    int t = threadIdx.x;
    int v = (t < nb) ? g_blocksum[t] : 0;
    bs[t] = v;
    __syncthreads();
#pragma unroll
    for (int off = 1; off < MAX_SCAN_BLOCKS; off <<= 1) {
        int u = (t >= off) ? bs[t - off] : 0;
        __syncthreads();
        bs[t] += u;
        __syncthreads();
    }
    if (t < nb) g_blockoff[t] = bs[t] - v;
}

__global__ void apply_offsets_kernel(int N, int E) {
    int i = blockIdx.x * blockDim.x + threadIdx.x;
    if (i < N) {
        int r = g_scanloc[i] + g_blockoff[i / SCAN_BLK];
        g_rowptr[i] = r;
        g_cursor[i] = r;
    }
    if (i == 0) g_rowptr[N] = E;
}

__global__ void fill_kernel(const int* __restrict__ ei, int E) {
    int e = blockIdx.x * blockDim.x + threadIdx.x;
    if (e < E) {
        int d = ei[E + e];
        int pos = atomicAdd(&g_cursor[d], 1);
        g_csr_src[pos] = ei[e];
    }
}

// ---------------- GEMM: ys = (A @ W) * dinv[row], f32x2 inner loop ----------
template <int KTOT>
__global__ __launch_bounds__(256) void gemm_scale(const float* __restrict__ A,
                                                  const float* __restrict__ W,
                                                  int N) {
    __shared__ float Ask[32][132];
    __shared__ float Ws[32][64];

    const float* __restrict__ Ap = A ? A : g_h;

    int tid = threadIdx.x;
    int tx = tid & 15;
    int ty = tid >> 4;
    int rowBase = blockIdx.x * 128;

    // acc2[i2][j] = {acc[2*i2][j], acc[2*i2+1][j]}  (rows paired)
    unsigned long long acc2[4][4];
#pragma unroll
    for (int i = 0; i < 4; i++)
#pragma unroll
        for (int j = 0; j < 4; j++) acc2[i][j] = 0ULL;

    for (int kc = 0; kc < KTOT; kc += 32) {
        {
            int k8 = tid & 7;
            int r0 = tid >> 3;
#pragma unroll
            for (int p = 0; p < 4; p++) {
                int r = r0 + p * 32;
                int grow = rowBase + r;
                float4 v = make_float4(0.f, 0.f, 0.f, 0.f);
                if (grow < N)
                    v = *(const float4*)(Ap + (size_t)grow * KTOT + kc + k8 * 4);
                Ask[k8 * 4 + 0][r] = v.x;
                Ask[k8 * 4 + 1][r] = v.y;
                Ask[k8 * 4 + 2][r] = v.z;
                Ask[k8 * 4 + 3][r] = v.w;
            }
        }
        {
            int c4 = tid & 15;
            int kr = tid >> 4;
#pragma unroll
            for (int p = 0; p < 2; p++) {
                int k = kr + p * 16;
                *(float4*)&Ws[k][c4 * 4] =
                    *(const float4*)(W + (size_t)(kc + k) * 64 + c4 * 4);
            }
        }
        __syncthreads();
#pragma unroll
        for (int kk = 0; kk < 32; kk++) {
            float4 w = *(const float4*)&Ws[kk][tx * 4];
            float4 a0 = *(const float4*)&Ask[kk][ty * 8];
            float4 a1 = *(const float4*)&Ask[kk][ty * 8 + 4];

            unsigned long long w2[4];
            w2[0] = pack2(w.x, w.x);
            w2[1] = pack2(w.y, w.y);
            w2[2] = pack2(w.z, w.z);
            w2[3] = pack2(w.w, w.w);

            unsigned long long a2[4];
            a2[0] = pack2(a0.x, a0.y);
            a2[1] = pack2(a0.z, a0.w);
            a2[2] = pack2(a1.x, a1.y);
            a2[3] = pack2(a1.z, a1.w);

#pragma unroll
            for (int i = 0; i < 4; i++)
#pragma unroll
                for (int j = 0; j < 4; j++) fma2(acc2[i][j], a2[i], w2[j]);
        }
        __syncthreads();
    }

#pragma unroll
    for (int i2 = 0; i2 < 4; i2++) {
#pragma unroll
        for (int sub = 0; sub < 2; sub++) {
            int row = rowBase + ty * 8 + i2 * 2 + sub;
            if (row < N) {
                float dv = g_dinv[row];
                float4 v;
                float lo, hi;
                unpack2(acc2[i2][0], lo, hi); v.x = (sub ? hi : lo) * dv;
                unpack2(acc2[i2][1], lo, hi); v.y = (sub ? hi : lo) * dv;
                unpack2(acc2[i2][2], lo, hi); v.z = (sub ? hi : lo) * dv;
                unpack2(acc2[i2][3], lo, hi); v.w = (sub ? hi : lo) * dv;
                *(float4*)(g_ys + (size_t)row * HID + tx * 4) = v;
            }
        }
    }
}

// ---- aggregation (pull) + fused pooling ------------------------------------
// h[n] = relu(dinv*(ys[n] + sum ys[src]) + b); optionally pool h into g_pooled.
__global__ __launch_bounds__(256) void aggregate_kernel(
    const float* __restrict__ bias, const int* __restrict__ batch,
    int off, int doPool, int doCount, int N) {
    int gid = blockIdx.x * blockDim.x + threadIdx.x;
    int node = gid >> 4;
    int f4 = (gid & 15) * 4;
    bool valid = node < N;

    float4 h = make_float4(0.f, 0.f, 0.f, 0.f);
    if (valid) {
        int beg = __ldg(&g_rowptr[node]);
        int end = __ldg(&g_rowptr[node + 1]);

        float4 s0 = *(const float4*)(g_ys + (size_t)node * HID + f4);  // self loop
        float4 s1 = make_float4(0.f, 0.f, 0.f, 0.f);
        float4 s2 = make_float4(0.f, 0.f, 0.f, 0.f);
        float4 s3 = make_float4(0.f, 0.f, 0.f, 0.f);

        int e = beg;
        for (; e + 4 <= end; e += 4) {
            int a = __ldg(&g_csr_src[e]);
            int b = __ldg(&g_csr_src[e + 1]);
            int c = __ldg(&g_csr_src[e + 2]);
            int d = __ldg(&g_csr_src[e + 3]);
            float4 v0 = *(const float4*)(g_ys + (size_t)a * HID + f4);
            float4 v1 = *(const float4*)(g_ys + (size_t)b * HID + f4);
            float4 v2 = *(const float4*)(g_ys + (size_t)c * HID + f4);
            float4 v3 = *(const float4*)(g_ys + (size_t)d * HID + f4);
            s0.x += v0.x; s0.y += v0.y; s0.z += v0.z; s0.w += v0.w;
            s1.x += v1.x; s1.y += v1.y; s1.z += v1.z; s1.w += v1.w;
            s2.x += v2.x; s2.y += v2.y; s2.z += v2.z; s2.w += v2.w;
            s3.x += v3.x; s3.y += v3.y; s3.z += v3.z; s3.w += v3.w;
        }
        for (; e < end; e++) {
            int a = __ldg(&g_csr_src[e]);
            float4 v = *(const float4*)(g_ys + (size_t)a * HID + f4);
            s0.x += v.x; s0.y += v.y; s0.z += v.z; s0.w += v.w;
        }
        s0.x += s1.x + s2.x + s3.x;
        s0.y += s1.y + s2.y + s3.y;
        s0.z += s1.z + s2.z + s3.z;
        s0.w += s1.w + s2.w + s3.w;

        float dv = g_dinv[node];
        float4 b4 = *(const float4*)(bias + f4);
        h.x = fmaxf(s0.x * dv + b4.x, 0.f);
        h.y = fmaxf(s0.y * dv + b4.y, 0.f);
        h.z = fmaxf(s0.z * dv + b4.z, 0.f);
        h.w = fmaxf(s0.w * dv + b4.w, 0.f);
        *(float4*)(g_h + (size_t)node * HID + f4) = h;
    }

    if (doPool) {
        __shared__ float sh[16][64];
        __shared__ int sg[16];
        int nl = threadIdx.x >> 4;
        int f4i = threadIdx.x & 15;
        *(float4*)&sh[nl][f4i * 4] = h;
        if (f4i == 0) sg[nl] = valid ? __ldg(&batch[node]) : -1;
        __syncthreads();

        if (threadIdx.x < 64) {
            int gmin = 0x7fffffff, gmax = -1;
#pragma unroll
            for (int i = 0; i < 16; i++) {
                int g = sg[i];
                if (g >= 0) { gmin = min(gmin, g); gmax = max(gmax, g); }
            }
            for (int g = gmin; g <= gmax; g++) {
                float s = 0.f;
                int cnt = 0;
#pragma unroll
                for (int i = 0; i < 16; i++)
                    if (sg[i] == g) { s += sh[i][threadIdx.x]; cnt++; }
                atomicAdd(&g_pooled[g * JKDIM + off + threadIdx.x], s);
                if (doCount && threadIdx.x == 0) atomicAdd(&g_cnt[g], (float)cnt);
            }
        }
    }
}

// ---------------- head: mean-pool normalize + linear + log_softmax ----------
__global__ void head_kernel(const float* __restrict__ Wl,
                            const float* __restrict__ bl,
                            float* __restrict__ out) {
    int g = threadIdx.x;
    if (g >= NGRAPHS) return;
    float ic = 1.f / fmaxf(g_cnt[g], 1.f);
    float logit[10];
#pragma unroll
    for (int j = 0; j < 10; j++) logit[j] = bl[j];
    for (int k = 0; k < JKDIM; k++) {
        float v = g_pooled[g * JKDIM + k] * ic;
#pragma unroll
        for (int j = 0; j < 10; j++) logit[j] += v * Wl[k * 10 + j];
    }
    float m = logit[0];
#pragma unroll
    for (int j = 1; j < 10; j++) m = fmaxf(m, logit[j]);
    float s = 0.f;
#pragma unroll
    for (int j = 0; j < 10; j++) s += expf(logit[j] - m);
    float lse = logf(s);
#pragma unroll
    for (int j = 0; j < 10; j++) out[g * 10 + j] = logit[j] - m - lse;
}

// ---------------- launch -----------------------------------------------------
extern "C" void kernel_launch(void* const* d_in, const int* in_sizes, int n_in,
                              void* d_out, int out_size) {
    const float* x  = (const float*)d_in[0];
    const float* W1 = (const float*)d_in[1];
    const float* b1 = (const float*)d_in[2];
    const float* W2 = (const float*)d_in[3];
    const float* b2 = (const float*)d_in[4];
    const float* W3 = (const float*)d_in[5];
    const float* b3 = (const float*)d_in[6];
    const float* W4 = (const float*)d_in[7];
    const float* b4 = (const float*)d_in[8];
    const float* Wl = (const float*)d_in[9];
    const float* bl = (const float*)d_in[10];
    const int* ei    = (const int*)d_in[11];
    const int* batch = (const int*)d_in[12];
    float* out = (float*)d_out;

    int N = in_sizes[12];
    int E = in_sizes[11] / 2;

    int threads = 256;
    int gridN = (N + threads - 1) / threads;
    int gridE = (E + threads - 1) / threads;
    int gemmGrid = (N + 127) / 128;
    int aggGrid = (N * 16 + threads - 1) / threads;
    int nScanBlocks = (N + SCAN_BLK - 1) / SCAN_BLK;

    zero_kernel<<<gridN, threads>>>(N);
    degree_kernel<<<gridE, threads>>>(ei, E);
    dinv_kernel<<<gridN, threads>>>(N);
    block_scan_kernel<<<nScanBlocks, SCAN_BLK>>>(N);
    scan_blocksums_kernel<<<1, MAX_SCAN_BLOCKS>>>(nScanBlocks);
    apply_offsets_kernel<<<gridN, threads>>>(N, E);
    fill_kernel<<<gridE, threads>>>(ei, E);

    // layer 1 (input x, K=128); pool x1 -> [0:64), also counts
    gemm_scale<128><<<gemmGrid, 256>>>(x, W1, N);
    aggregate_kernel<<<aggGrid, threads>>>(b1, batch, 0, 1, 1, N);

    // layer 2; pool x2 -> [64:128)
    gemm_scale<64><<<gemmGrid, 256>>>(nullptr, W2, N);
    aggregate_kernel<<<aggGrid, threads>>>(b2, batch, 64, 1, 0, N);

    // layer 3 (no pool)
    gemm_scale<64><<<gemmGrid, 256>>>(nullptr, W3, N);
    aggregate_kernel<<<aggGrid, threads>>>(b3, batch, 0, 0, 0, N);

    // layer 4 (overwrites x3, as in reference); pool -> [128:192)
    gemm_scale<64><<<gemmGrid, 256>>>(nullptr, W4, N);
    aggregate_kernel<<<aggGrid, threads>>>(b4, batch, 128, 1, 0, N);

    head_kernel<<<1, 64>>>(Wl, bl, out);
}